// round 2
// baseline (speedup 1.0000x reference)
#include <cuda_runtime.h>

typedef unsigned long long u64;

#define B_    16384
#define N_    128
#define DIR_  16
#define KGEO  18
#define NBLK  2048
#define NTHR  128

// ---------- packed f32x2 helpers (FFMA2 path, PTX-only) ----------
static __device__ __forceinline__ u64 ffma2(u64 a, u64 b, u64 c) {
    u64 d;
    asm("fma.rn.f32x2 %0, %1, %2, %3;" : "=l"(d) : "l"(a), "l"(b), "l"(c));
    return d;
}
static __device__ __forceinline__ u64 pack2(float x) {
    u64 r; unsigned xi = __float_as_uint(x);
    asm("mov.b64 %0, {%1, %1};" : "=l"(r) : "r"(xi));
    return r;
}
static __device__ __forceinline__ u64 pack2f(float a, float b) {
    u64 r;
    asm("mov.b64 %0, {%1, %2};" : "=l"(r)
        : "r"(__float_as_uint(a)), "r"(__float_as_uint(b)));
    return r;
}
static __device__ __forceinline__ void unpack2(u64 v, float& a, float& b) {
    unsigned lo, hi;
    asm("mov.b64 {%0, %1}, %2;" : "=r"(lo), "=r"(hi) : "l"(v));
    a = __uint_as_float(lo); b = __uint_as_float(hi);
}

// Shared-memory layout (dynamic; every member is 16B-aligned: all sizes mult of 16)
struct Smem {
    float W0[34 * 64];     // [k][j]
    float W1[64 * 64];     // [k][j]
    u64   W2p[64];         // W2 cols (0,1) packed
    float W2z[64];         // W2 col 2
    float B0[64];
    float B1[64];          // read as u64 pairs
    float B2[4];
    float D[16];
    float Pre0[64];        // b0 + d@W0[0:16]  (read as u64 pairs)
    float Geo[KGEO * 128]; // transposed [k][point]
    float Act[64 * 128];   // transposed [col][point]
    float Sig[128];
    float Max[4];
    float CRed[12];
};

// One k-step of the register-tiled GEMM: 4 points x 16 cols (as 8 FFMA2 pairs)
static __device__ __forceinline__ void gemm_step(
    const float* __restrict__ act, const float* __restrict__ w,
    u64 acc[4][8], int k, int p0, int c0)
{
    float4 a = *(const float4*)(act + k * 128 + p0);           // 4 points at this k
    const ulonglong2* wr = (const ulonglong2*)(w + k * 64 + c0); // 16 cols
    ulonglong2 w0 = wr[0], w1 = wr[1], w2 = wr[2], w3 = wr[3];
    u64 wv0 = w0.x, wv1 = w0.y, wv2 = w1.x, wv3 = w1.y;
    u64 wv4 = w2.x, wv5 = w2.y, wv6 = w3.x, wv7 = w3.y;
    u64 a0 = pack2(a.x), a1 = pack2(a.y), a2 = pack2(a.z), a3 = pack2(a.w);
    acc[0][0] = ffma2(a0, wv0, acc[0][0]); acc[1][0] = ffma2(a1, wv0, acc[1][0]);
    acc[2][0] = ffma2(a2, wv0, acc[2][0]); acc[3][0] = ffma2(a3, wv0, acc[3][0]);
    acc[0][1] = ffma2(a0, wv1, acc[0][1]); acc[1][1] = ffma2(a1, wv1, acc[1][1]);
    acc[2][1] = ffma2(a2, wv1, acc[2][1]); acc[3][1] = ffma2(a3, wv1, acc[3][1]);
    acc[0][2] = ffma2(a0, wv2, acc[0][2]); acc[1][2] = ffma2(a1, wv2, acc[1][2]);
    acc[2][2] = ffma2(a2, wv2, acc[2][2]); acc[3][2] = ffma2(a3, wv2, acc[3][2]);
    acc[0][3] = ffma2(a0, wv3, acc[0][3]); acc[1][3] = ffma2(a1, wv3, acc[1][3]);
    acc[2][3] = ffma2(a2, wv3, acc[2][3]); acc[3][3] = ffma2(a3, wv3, acc[3][3]);
    acc[0][4] = ffma2(a0, wv4, acc[0][4]); acc[1][4] = ffma2(a1, wv4, acc[1][4]);
    acc[2][4] = ffma2(a2, wv4, acc[2][4]); acc[3][4] = ffma2(a3, wv4, acc[3][4]);
    acc[0][5] = ffma2(a0, wv5, acc[0][5]); acc[1][5] = ffma2(a1, wv5, acc[1][5]);
    acc[2][5] = ffma2(a2, wv5, acc[2][5]); acc[3][5] = ffma2(a3, wv5, acc[3][5]);
    acc[0][6] = ffma2(a0, wv6, acc[0][6]); acc[1][6] = ffma2(a1, wv6, acc[1][6]);
    acc[2][6] = ffma2(a2, wv6, acc[2][6]); acc[3][6] = ffma2(a3, wv6, acc[3][6]);
    acc[0][7] = ffma2(a0, wv7, acc[0][7]); acc[1][7] = ffma2(a1, wv7, acc[1][7]);
    acc[2][7] = ffma2(a2, wv7, acc[2][7]); acc[3][7] = ffma2(a3, wv7, acc[3][7]);
}

// ReLU + transposed store of the 4x16 tile into Act[col][point]
static __device__ __forceinline__ void relu_store(
    u64 acc[4][8], float* __restrict__ dst, int p0, int c0)
{
    #pragma unroll
    for (int j = 0; j < 8; j++) {
        float l0, h0, l1, h1, l2, h2, l3, h3;
        unpack2(acc[0][j], l0, h0);
        unpack2(acc[1][j], l1, h1);
        unpack2(acc[2][j], l2, h2);
        unpack2(acc[3][j], l3, h3);
        float4 lo = make_float4(fmaxf(l0, 0.f), fmaxf(l1, 0.f),
                                fmaxf(l2, 0.f), fmaxf(l3, 0.f));
        float4 hi = make_float4(fmaxf(h0, 0.f), fmaxf(h1, 0.f),
                                fmaxf(h2, 0.f), fmaxf(h3, 0.f));
        *(float4*)(dst + (c0 + 2 * j) * 128 + p0) = lo;
        *(float4*)(dst + (c0 + 2 * j + 1) * 128 + p0) = hi;
    }
}

__global__ void __launch_bounds__(NTHR, 3)
surfnet_kernel(const int*    __restrict__ x,
               const float*  __restrict__ dirg,
               const float4* __restrict__ gw,
               const float*  __restrict__ W0, const float* __restrict__ b0,
               const float*  __restrict__ W1, const float* __restrict__ b1,
               const float*  __restrict__ W2, const float* __restrict__ b2,
               float* __restrict__ outSigma, float* __restrict__ outColor)
{
    extern __shared__ __align__(16) char smem_raw[];
    Smem& S = *reinterpret_cast<Smem*>(smem_raw);

    const int tid  = threadIdx.x;
    const int lane = tid & 31;
    const int warp = tid >> 5;
    const int pg = tid >> 2, cg = tid & 3;
    const int p0 = pg * 4,   c0 = cg * 16;

    // ---- stage weights in shared (once per block) ----
    for (int i = tid; i < 34 * 64; i += NTHR) S.W0[i] = W0[i];
    for (int i = tid; i < 64 * 64; i += NTHR) S.W1[i] = W1[i];
    if (tid < 64) {
        S.B0[tid] = b0[tid];
        S.B1[tid] = b1[tid];
        S.W2p[tid] = pack2f(W2[tid * 3 + 0], W2[tid * 3 + 1]);
        S.W2z[tid] = W2[tid * 3 + 2];
    }
    if (tid < 3) S.B2[tid] = b2[tid];
    __syncthreads();

    for (int row = blockIdx.x; row < B_; row += NBLK) {
        // ---- phase A: gather (thread = point), sigma, geo staging ----
        if (tid < DIR_) S.D[tid] = dirg[(size_t)row * DIR_ + tid];

        const int2* xr = ((const int2*)x) + ((size_t)row * N_ + tid) * 3;
        int2 i01 = xr[0], i23 = xr[1], i45 = xr[2];
        float4 f0 = __ldg(gw + i01.x);
        float4 f1 = __ldg(gw + i01.y);
        float4 f2 = __ldg(gw + i23.x);
        float4 f3 = __ldg(gw + i23.y);
        float4 f4 = __ldg(gw + i45.x);
        float4 f5 = __ldg(gw + i45.y);

        S.Geo[ 0 * 128 + tid] = f0.y; S.Geo[ 1 * 128 + tid] = f0.z; S.Geo[ 2 * 128 + tid] = f0.w;
        S.Geo[ 3 * 128 + tid] = f1.y; S.Geo[ 4 * 128 + tid] = f1.z; S.Geo[ 5 * 128 + tid] = f1.w;
        S.Geo[ 6 * 128 + tid] = f2.y; S.Geo[ 7 * 128 + tid] = f2.z; S.Geo[ 8 * 128 + tid] = f2.w;
        S.Geo[ 9 * 128 + tid] = f3.y; S.Geo[10 * 128 + tid] = f3.z; S.Geo[11 * 128 + tid] = f3.w;
        S.Geo[12 * 128 + tid] = f4.y; S.Geo[13 * 128 + tid] = f4.z; S.Geo[14 * 128 + tid] = f4.w;
        S.Geo[15 * 128 + tid] = f5.y; S.Geo[16 * 128 + tid] = f5.z; S.Geo[17 * 128 + tid] = f5.w;

        float s = fminf(fmaxf(f0.x, 0.f), 1.f);
        s *= fminf(fmaxf(f1.x, 0.f), 1.f);
        s *= fminf(fmaxf(f2.x, 0.f), 1.f);
        s *= fminf(fmaxf(f3.x, 0.f), 1.f);
        s *= fminf(fmaxf(f4.x, 0.f), 1.f);
        s *= fminf(fmaxf(f5.x, 0.f), 1.f);
        float sigma0 = s + 1e-4f;

        float m = sigma0;
        #pragma unroll
        for (int o = 16; o > 0; o >>= 1)
            m = fmaxf(m, __shfl_xor_sync(0xffffffffu, m, o));
        if (lane == 0) S.Max[warp] = m;
        __syncthreads();  // [1] Geo, D, Max ready

        // ---- phase B: normalize sigma, hoisted dir half of layer 0 ----
        float rowmax = fmaxf(fmaxf(S.Max[0], S.Max[1]), fmaxf(S.Max[2], S.Max[3]));
        float sigma = sigma0 / rowmax;
        S.Sig[tid] = sigma;
        outSigma[(size_t)row * N_ + tid] = sigma;

        if (tid < 64) {
            float a = S.B0[tid];
            #pragma unroll
            for (int k = 0; k < DIR_; k++)
                a = fmaf(S.D[k], S.W0[k * 64 + tid], a);
            S.Pre0[tid] = a;
        }
        __syncthreads();  // [2] Pre0, Sig ready

        // ---- GEMM0: (geo 18) -> 64, tile 4 points x 16 cols ----
        u64 acc[4][8];
        {
            const ulonglong2* pr = (const ulonglong2*)((const u64*)S.Pre0 + cg * 8);
            ulonglong2 q0 = pr[0], q1 = pr[1], q2 = pr[2], q3 = pr[3];
            u64 pre[8] = {q0.x, q0.y, q1.x, q1.y, q2.x, q2.y, q3.x, q3.y};
            #pragma unroll
            for (int pp = 0; pp < 4; pp++)
                #pragma unroll
                for (int j = 0; j < 8; j++) acc[pp][j] = pre[j];
        }
        const float* w0g = S.W0 + DIR_ * 64;
        #pragma unroll
        for (int k = 0; k < KGEO; k++) gemm_step(S.Geo, w0g, acc, k, p0, c0);
        relu_store(acc, S.Act, p0, c0);
        __syncthreads();  // [3] Act (layer-0 out) ready

        // ---- GEMM1: 64 -> 64 ----
        {
            const ulonglong2* br = (const ulonglong2*)((const u64*)S.B1 + cg * 8);
            ulonglong2 q0 = br[0], q1 = br[1], q2 = br[2], q3 = br[3];
            u64 bb[8] = {q0.x, q0.y, q1.x, q1.y, q2.x, q2.y, q3.x, q3.y};
            #pragma unroll
            for (int pp = 0; pp < 4; pp++)
                #pragma unroll
                for (int j = 0; j < 8; j++) acc[pp][j] = bb[j];
        }
        #pragma unroll 8
        for (int k = 0; k < 64; k++) gemm_step(S.Act, S.W1, acc, k, p0, c0);
        __syncthreads();  // [4] all reads of Act complete before overwrite
        relu_store(acc, S.Act, p0, c0);
        __syncthreads();  // [5] Act (layer-1 out) ready

        // ---- layer 2: 64 -> 3 (thread = point) ----
        u64 a01 = pack2f(S.B2[0], S.B2[1]);
        float a2c = S.B2[2];
        #pragma unroll 8
        for (int k = 0; k < 64; k++) {
            float a = S.Act[k * 128 + tid];
            a01 = ffma2(pack2(a), S.W2p[k], a01);
            a2c = fmaf(a, S.W2z[k], a2c);
        }
        float cA, cB;
        unpack2(a01, cA, cB);
        cA = 1.f / (1.f + __expf(-cA));
        cB = 1.f / (1.f + __expf(-cB));
        float cC = 1.f / (1.f + __expf(-a2c));

        // ---- compositing + per-row color reduction ----
        float wgt = (tid == 0 ? 1.f : 1.f - S.Sig[tid - 1]) * sigma;
        float r0 = wgt * cA, r1 = wgt * cB, r2 = wgt * cC;
        #pragma unroll
        for (int o = 16; o > 0; o >>= 1) {
            r0 += __shfl_xor_sync(0xffffffffu, r0, o);
            r1 += __shfl_xor_sync(0xffffffffu, r1, o);
            r2 += __shfl_xor_sync(0xffffffffu, r2, o);
        }
        if (lane == 0) {
            S.CRed[warp * 3 + 0] = r0;
            S.CRed[warp * 3 + 1] = r1;
            S.CRed[warp * 3 + 2] = r2;
        }
        __syncthreads();  // [6] CRed ready
        if (tid == 0) {
            float t0 = S.CRed[0] + S.CRed[3] + S.CRed[6] + S.CRed[9];
            float t1 = S.CRed[1] + S.CRed[4] + S.CRed[7] + S.CRed[10];
            float t2 = S.CRed[2] + S.CRed[5] + S.CRed[8] + S.CRed[11];
            float* oc = outColor + (size_t)row * 3;
            oc[0] = t0; oc[1] = t1; oc[2] = t2;
        }
        // No extra barrier needed: every shared region written early in the next
        // iteration had its last read before an earlier barrier this iteration.
    }
}

extern "C" void kernel_launch(void* const* d_in, const int* in_sizes, int n_in,
                              void* d_out, int out_size)
{
    const int*    x    = (const int*)d_in[0];
    const float*  dirg = (const float*)d_in[1];
    const float4* gw   = (const float4*)d_in[2];
    const float*  W0   = (const float*)d_in[3];
    const float*  b0   = (const float*)d_in[4];
    const float*  W1   = (const float*)d_in[5];
    const float*  b1   = (const float*)d_in[6];
    const float*  W2   = (const float*)d_in[7];
    const float*  b2   = (const float*)d_in[8];

    float* outSigma = (float*)d_out;                  // (B, N, 1) flattened
    float* outColor = outSigma + (size_t)B_ * N_;     // (B, 3) flattened

    int smem = (int)sizeof(Smem);
    cudaFuncSetAttribute(surfnet_kernel,
                         cudaFuncAttributeMaxDynamicSharedMemorySize, smem);
    surfnet_kernel<<<NBLK, NTHR, smem>>>(x, dirg, gw, W0, b0, W1, b1, W2, b2,
                                         outSigma, outColor);
}

// round 7
// speedup vs baseline: 1.3934x; 1.3934x over previous
#include <cuda_runtime.h>

typedef unsigned long long u64;

#define B_    16384
#define N_    128
#define DIR_  16
#define KGEO  18
#define NBLK  2048
#define NTHR  128

// ---------- packed f32x2 helpers (FFMA2 path, PTX-only) ----------
static __device__ __forceinline__ u64 ffma2(u64 a, u64 b, u64 c) {
    u64 d;
    asm("fma.rn.f32x2 %0, %1, %2, %3;" : "=l"(d) : "l"(a), "l"(b), "l"(c));
    return d;
}
static __device__ __forceinline__ u64 pack2(float x) {
    u64 r; unsigned xi = __float_as_uint(x);
    asm("mov.b64 %0, {%1, %1};" : "=l"(r) : "r"(xi));
    return r;
}
static __device__ __forceinline__ u64 pack2f(float a, float b) {
    u64 r;
    asm("mov.b64 %0, {%1, %2};" : "=l"(r)
        : "r"(__float_as_uint(a)), "r"(__float_as_uint(b)));
    return r;
}
static __device__ __forceinline__ void unpack2(u64 v, float& a, float& b) {
    unsigned lo, hi;
    asm("mov.b64 {%0, %1}, %2;" : "=r"(lo), "=r"(hi) : "l"(v));
    a = __uint_as_float(lo); b = __uint_as_float(hi);
}

// All members 16B-friendly sizes; struct carried in dynamic smem (~74 KB -> 3 CTAs/SM)
struct Smem {
    float  W0full[34 * 64];  // [k][c]  rows 0-15 dir, 16-33 geo
    float  W1s[64 * 64];     // [k][c]
    float  Pre0[64];         // b0 + d @ W0[0:16]
    float  B0c[64];
    float  B1c[64];
    float4 W2q[64];          // (w2c0, w2c1, w2c2, 0)
    float  B2[4];
    float  D[DIR_];
    float  Max[4];
    float  Sig[N_];
    float  Geo[KGEO * 128];  // [k][point]
    float  Act[64 * 128];    // [c][point], written/read as (p0,p1) u64 pairs
    float4 PSum[256];        // [point][cg] layer-2 partials
    float  CRed[12];
};

__global__ void __launch_bounds__(NTHR)
surfnet_kernel(const int*    __restrict__ x,
               const float*  __restrict__ dirg,
               const float4* __restrict__ gw,
               const float*  __restrict__ W0, const float* __restrict__ b0,
               const float*  __restrict__ W1, const float* __restrict__ b1,
               const float*  __restrict__ W2, const float* __restrict__ b2,
               float* __restrict__ outSigma, float* __restrict__ outColor)
{
    extern __shared__ __align__(16) char smem_raw[];
    Smem& S = *reinterpret_cast<Smem*>(smem_raw);

    const int tid  = threadIdx.x;
    const int lane = tid & 31;
    const int warp = tid >> 5;
    // GEMM mapping: warps {0,1} -> cols 0..31, warps {2,3} -> cols 32..63.
    // Lanes span point-pairs; each thread owns 2 points x 32 cols.
    const int cg    = warp >> 1;                  // column group
    const int pairi = ((warp & 1) << 5) | lane;   // 0..63
    const int p0    = pairi * 2;                  // first point of the pair
    const int cbase = cg * 32;

    // ---- stage weights in shared (once per block) ----
    for (int i = tid; i < 34 * 64; i += NTHR) S.W0full[i] = W0[i];
    for (int i = tid; i < 64 * 64; i += NTHR) S.W1s[i] = W1[i];
    if (tid < 64) {
        S.B0c[tid] = b0[tid];
        S.B1c[tid] = b1[tid];
        S.W2q[tid] = make_float4(W2[tid * 3], W2[tid * 3 + 1], W2[tid * 3 + 2], 0.f);
    }
    if (tid < 3) S.B2[tid] = b2[tid];
    __syncthreads();

    for (int row = blockIdx.x; row < B_; row += NBLK) {
        // ================= phase A: gather (thread = point) =================
        if (tid < DIR_) S.D[tid] = dirg[(size_t)row * DIR_ + tid];

        const int2* xr = ((const int2*)x) + ((size_t)row * N_ + tid) * 3;
        int2 i01 = xr[0], i23 = xr[1], i45 = xr[2];
        float4 f0 = __ldg(gw + i01.x);
        float4 f1 = __ldg(gw + i01.y);
        float4 f2 = __ldg(gw + i23.x);
        float4 f3 = __ldg(gw + i23.y);
        float4 f4 = __ldg(gw + i45.x);
        float4 f5 = __ldg(gw + i45.y);

        S.Geo[ 0 * 128 + tid] = f0.y; S.Geo[ 1 * 128 + tid] = f0.z; S.Geo[ 2 * 128 + tid] = f0.w;
        S.Geo[ 3 * 128 + tid] = f1.y; S.Geo[ 4 * 128 + tid] = f1.z; S.Geo[ 5 * 128 + tid] = f1.w;
        S.Geo[ 6 * 128 + tid] = f2.y; S.Geo[ 7 * 128 + tid] = f2.z; S.Geo[ 8 * 128 + tid] = f2.w;
        S.Geo[ 9 * 128 + tid] = f3.y; S.Geo[10 * 128 + tid] = f3.z; S.Geo[11 * 128 + tid] = f3.w;
        S.Geo[12 * 128 + tid] = f4.y; S.Geo[13 * 128 + tid] = f4.z; S.Geo[14 * 128 + tid] = f4.w;
        S.Geo[15 * 128 + tid] = f5.y; S.Geo[16 * 128 + tid] = f5.z; S.Geo[17 * 128 + tid] = f5.w;

        float s = fminf(fmaxf(f0.x, 0.f), 1.f);
        s *= fminf(fmaxf(f1.x, 0.f), 1.f);
        s *= fminf(fmaxf(f2.x, 0.f), 1.f);
        s *= fminf(fmaxf(f3.x, 0.f), 1.f);
        s *= fminf(fmaxf(f4.x, 0.f), 1.f);
        s *= fminf(fmaxf(f5.x, 0.f), 1.f);
        float sigma0 = s + 1e-4f;

        float m = sigma0;
        #pragma unroll
        for (int o = 16; o > 0; o >>= 1)
            m = fmaxf(m, __shfl_xor_sync(0xffffffffu, m, o));
        if (lane == 0) S.Max[warp] = m;
        __syncthreads();  // [1] Geo, D, Max ready

        float rowmax = fmaxf(fmaxf(S.Max[0], S.Max[1]), fmaxf(S.Max[2], S.Max[3]));
        float sigma = sigma0 / rowmax;
        S.Sig[tid] = sigma;
        outSigma[(size_t)row * N_ + tid] = sigma;

        if (tid < 64) {   // hoisted direction half of layer 0
            float a = S.B0c[tid];
            #pragma unroll
            for (int k = 0; k < DIR_; k++)
                a = fmaf(S.D[k], S.W0full[k * 64 + tid], a);
            S.Pre0[tid] = a;
        }
        __syncthreads();  // [2] Pre0, Sig ready

        // ================= GEMM0: geo(18) -> 64, tile 2p x 32c =================
        u64 acc0[16], acc1[16];   // col-pairs for point p0 / p0+1
        {
            const u64* pre = (const u64*)(S.Pre0 + cbase);
            #pragma unroll
            for (int j = 0; j < 16; j++) { acc0[j] = pre[j]; acc1[j] = pre[j]; }
        }
        #pragma unroll 6
        for (int k = 0; k < KGEO; k++) {
            u64 av = *(const u64*)(S.Geo + k * 128 + p0);
            float a0f, a1f; unpack2(av, a0f, a1f);
            u64 a0 = pack2(a0f), a1 = pack2(a1f);
            const ulonglong2* wr =
                (const ulonglong2*)(S.W0full + (DIR_ + k) * 64 + cbase);
            #pragma unroll
            for (int jj = 0; jj < 8; jj++) {
                ulonglong2 w = wr[jj];
                acc0[2 * jj]     = ffma2(a0, w.x, acc0[2 * jj]);
                acc0[2 * jj + 1] = ffma2(a0, w.y, acc0[2 * jj + 1]);
                acc1[2 * jj]     = ffma2(a1, w.x, acc1[2 * jj]);
                acc1[2 * jj + 1] = ffma2(a1, w.y, acc1[2 * jj + 1]);
            }
        }
        // ReLU + stage as (p0,p1) u64 pairs into Act[c][point]
        #pragma unroll
        for (int j = 0; j < 16; j++) {
            float x0, x1, y0, y1;
            unpack2(acc0[j], x0, x1);
            unpack2(acc1[j], y0, y1);
            x0 = fmaxf(x0, 0.f); x1 = fmaxf(x1, 0.f);
            y0 = fmaxf(y0, 0.f); y1 = fmaxf(y1, 0.f);
            int c = cbase + 2 * j;
            *(u64*)(S.Act + c * 128 + p0)       = pack2f(x0, y0);
            *(u64*)(S.Act + (c + 1) * 128 + p0) = pack2f(x1, y1);
        }
        __syncthreads();  // [3] Act (layer-0 out) ready

        // ================= GEMM1: 64 -> 64 =================
        {
            const u64* bb = (const u64*)(S.B1c + cbase);
            #pragma unroll
            for (int j = 0; j < 16; j++) { acc0[j] = bb[j]; acc1[j] = bb[j]; }
        }
        #pragma unroll 4
        for (int k = 0; k < 64; k++) {
            u64 av = *(const u64*)(S.Act + k * 128 + p0);
            float a0f, a1f; unpack2(av, a0f, a1f);
            u64 a0 = pack2(a0f), a1 = pack2(a1f);
            const ulonglong2* wr = (const ulonglong2*)(S.W1s + k * 64 + cbase);
            #pragma unroll
            for (int jj = 0; jj < 8; jj++) {
                ulonglong2 w = wr[jj];
                acc0[2 * jj]     = ffma2(a0, w.x, acc0[2 * jj]);
                acc0[2 * jj + 1] = ffma2(a0, w.y, acc0[2 * jj + 1]);
                acc1[2 * jj]     = ffma2(a1, w.x, acc1[2 * jj]);
                acc1[2 * jj + 1] = ffma2(a1, w.y, acc1[2 * jj + 1]);
            }
        }

        // ================= layer 2 partials (ReLU fused) =================
        float s0a = 0.f, s1a = 0.f, s2a = 0.f;
        float s0b = 0.f, s1b = 0.f, s2b = 0.f;
        #pragma unroll
        for (int j = 0; j < 16; j++) {
            float x0, x1, y0, y1;
            unpack2(acc0[j], x0, x1);
            unpack2(acc1[j], y0, y1);
            x0 = fmaxf(x0, 0.f); x1 = fmaxf(x1, 0.f);
            y0 = fmaxf(y0, 0.f); y1 = fmaxf(y1, 0.f);
            float4 q0 = S.W2q[cbase + 2 * j];
            float4 q1 = S.W2q[cbase + 2 * j + 1];
            s0a = fmaf(x0, q0.x, s0a); s0a = fmaf(x1, q1.x, s0a);
            s1a = fmaf(x0, q0.y, s1a); s1a = fmaf(x1, q1.y, s1a);
            s2a = fmaf(x0, q0.z, s2a); s2a = fmaf(x1, q1.z, s2a);
            s0b = fmaf(y0, q0.x, s0b); s0b = fmaf(y1, q1.x, s0b);
            s1b = fmaf(y0, q0.y, s1b); s1b = fmaf(y1, q1.y, s1b);
            s2b = fmaf(y0, q0.z, s2b); s2b = fmaf(y1, q1.z, s2b);
        }
        S.PSum[p0 * 2 + cg]       = make_float4(s0a, s1a, s2a, 0.f);
        S.PSum[(p0 + 1) * 2 + cg] = make_float4(s0b, s1b, s2b, 0.f);
        __syncthreads();  // [4] PSum ready

        // ================= finish (thread = point) =================
        float4 pa = S.PSum[tid * 2];
        float4 pb = S.PSum[tid * 2 + 1];
        float c0 = pa.x + pb.x + S.B2[0];
        float c1 = pa.y + pb.y + S.B2[1];
        float c2 = pa.z + pb.z + S.B2[2];
        c0 = 1.f / (1.f + __expf(-c0));
        c1 = 1.f / (1.f + __expf(-c1));
        c2 = 1.f / (1.f + __expf(-c2));

        float wgt = (tid == 0 ? 1.f : 1.f - S.Sig[tid - 1]) * sigma;
        float r0 = wgt * c0, r1 = wgt * c1, r2 = wgt * c2;
        #pragma unroll
        for (int o = 16; o > 0; o >>= 1) {
            r0 += __shfl_xor_sync(0xffffffffu, r0, o);
            r1 += __shfl_xor_sync(0xffffffffu, r1, o);
            r2 += __shfl_xor_sync(0xffffffffu, r2, o);
        }
        if (lane == 0) {
            S.CRed[warp * 3 + 0] = r0;
            S.CRed[warp * 3 + 1] = r1;
            S.CRed[warp * 3 + 2] = r2;
        }
        __syncthreads();  // [5] CRed ready; guards Sig/Geo reuse next row
        if (tid == 0) {
            float* oc = outColor + (size_t)row * 3;
            oc[0] = S.CRed[0] + S.CRed[3] + S.CRed[6] + S.CRed[9];
            oc[1] = S.CRed[1] + S.CRed[4] + S.CRed[7] + S.CRed[10];
            oc[2] = S.CRed[2] + S.CRed[5] + S.CRed[8] + S.CRed[11];
        }
    }
}

extern "C" void kernel_launch(void* const* d_in, const int* in_sizes, int n_in,
                              void* d_out, int out_size)
{
    const int*    x    = (const int*)d_in[0];
    const float*  dirg = (const float*)d_in[1];
    const float4* gw   = (const float4*)d_in[2];
    const float*  W0   = (const float*)d_in[3];
    const float*  b0   = (const float*)d_in[4];
    const float*  W1   = (const float*)d_in[5];
    const float*  b1   = (const float*)d_in[6];
    const float*  W2   = (const float*)d_in[7];
    const float*  b2   = (const float*)d_in[8];

    float* outSigma = (float*)d_out;                  // (B, N, 1) flattened
    float* outColor = outSigma + (size_t)B_ * N_;     // (B, 3) flattened

    int smem = (int)sizeof(Smem);
    cudaFuncSetAttribute(surfnet_kernel,
                         cudaFuncAttributeMaxDynamicSharedMemorySize, smem);
    surfnet_kernel<<<NBLK, NTHR, smem>>>(x, dirg, gw, W0, b0, W1, b1, W2, b2,
                                         outSigma, outColor);
}

// round 15
// speedup vs baseline: 1.5651x; 1.1232x over previous
#include <cuda_runtime.h>

typedef unsigned long long u64;

#define B_    16384
#define N_    128
#define DIR_  16
#define KGEO  18
#define NBLK  2048
#define NTHR  128

__device__ __align__(16) float g_Pre[(size_t)B_ * 64];

// ---------- packed f32x2 helpers (FFMA2 path, PTX-only) ----------
static __device__ __forceinline__ u64 ffma2(u64 a, u64 b, u64 c) {
    u64 d;
    asm("fma.rn.f32x2 %0, %1, %2, %3;" : "=l"(d) : "l"(a), "l"(b), "l"(c));
    return d;
}
static __device__ __forceinline__ u64 pack2(float x) {
    u64 r; unsigned xi = __float_as_uint(x);
    asm("mov.b64 %0, {%1, %1};" : "=l"(r) : "r"(xi));
    return r;
}
static __device__ __forceinline__ u64 pack2f(float a, float b) {
    u64 r;
    asm("mov.b64 %0, {%1, %2};" : "=l"(r)
        : "r"(__float_as_uint(a)), "r"(__float_as_uint(b)));
    return r;
}
static __device__ __forceinline__ void unpack2(u64 v, float& a, float& b) {
    unsigned lo, hi;
    asm("mov.b64 {%0, %1}, %2;" : "=r"(lo), "=r"(hi) : "l"(v));
    a = __uint_as_float(lo); b = __uint_as_float(hi);
}
static __device__ __forceinline__ unsigned smem_u32(const void* p) {
    unsigned a;
    asm("{ .reg .u64 t; cvta.to.shared.u64 t, %1; cvt.u32.u64 %0, t; }"
        : "=r"(a) : "l"(p));
    return a;
}
static __device__ __forceinline__ void cp_async16(unsigned s, const void* g) {
    asm volatile("cp.async.ca.shared.global [%0], [%1], 16;"
                 :: "r"(s), "l"(g) : "memory");
}

// ---------------- pre-kernel: g_Pre[row][c] = b0[c] + d[row] @ W0[0:16] --------
__global__ void __launch_bounds__(128)
pre_kernel(const float* __restrict__ dirg,
           const float* __restrict__ W0, const float* __restrict__ b0)
{
    __shared__ float sd[2][DIR_];
    int tid = threadIdx.x;
    int rloc = tid >> 6, c = tid & 63;
    int row = blockIdx.x * 2 + rloc;
    if (tid < 32)
        sd[tid >> 4][tid & 15] = dirg[(size_t)(blockIdx.x * 2 + (tid >> 4)) * DIR_ + (tid & 15)];
    __syncthreads();
    float a = b0[c];
    #pragma unroll
    for (int k = 0; k < DIR_; k++)
        a = fmaf(sd[rloc][k], W0[k * 64 + c], a);
    g_Pre[(size_t)row * 64 + c] = a;
}

// ---------------- main kernel -------------------------------------------------
// smem ~69 KB -> 3 CTAs/SM; float4 members first for 16B alignment
struct Smem {
    float4 W2q[64];          // (w2c0, w2c1, w2c2, 0)
    float4 PSum[256];        // [point][cg] layer-2 partials
    float  W0geo[KGEO * 64]; // [k][c], geo rows only
    float  W1s[64 * 64];     // [k][c]
    float  B1c[64];
    float  B2[4];
    float  PreBuf[64];       // cp.async landing zone for g_Pre row
    float  Max[4];
    float  Sig[N_];
    float  Geo[KGEO * 128];  // [k][point]
    float  Act[64 * 128];    // [c][point], (p0,p1) u64 pairs
    float  CRed[12];
};

__global__ void __launch_bounds__(NTHR, 3)
surfnet_kernel(const int*    __restrict__ x,
               const float4* __restrict__ gw,
               const float*  __restrict__ W0, const float* __restrict__ b0,
               const float*  __restrict__ W1, const float* __restrict__ b1,
               const float*  __restrict__ W2, const float* __restrict__ b2,
               float* __restrict__ outSigma, float* __restrict__ outColor)
{
    extern __shared__ __align__(16) char smem_raw[];
    Smem& S = *reinterpret_cast<Smem*>(smem_raw);

    const int tid  = threadIdx.x;
    const int lane = tid & 31;
    const int warp = tid >> 5;
    // warps {0,1} -> cols 0..31, warps {2,3} -> cols 32..63; thread = 2 points x 32 cols
    const int cg    = warp >> 1;
    const int pairi = ((warp & 1) << 5) | lane;
    const int p0    = pairi * 2;
    const int cbase = cg * 32;

    // ---- stage weights (once per block) ----
    for (int i = tid; i < KGEO * 64; i += NTHR) S.W0geo[i] = W0[(DIR_ + i / 64) * 64 + (i & 63)];
    for (int i = tid; i < 64 * 64; i += NTHR)   S.W1s[i] = W1[i];
    if (tid < 64) {
        S.B1c[tid] = b1[tid];
        S.W2q[tid] = make_float4(W2[tid * 3], W2[tid * 3 + 1], W2[tid * 3 + 2], 0.f);
    }
    if (tid < 3) S.B2[tid] = b2[tid];
    const unsigned preb = smem_u32(S.PreBuf);

    // ---- prologue: prefetch row0 gather + Pre ----
    int row = blockIdx.x;
    const int2* xr0 = ((const int2*)x) + ((size_t)row * N_ + tid) * 3;
    int2 xi0 = xr0[0], xi1 = xr0[1], xi2 = xr0[2];
    float4 f0 = __ldg(gw + xi0.x);
    float4 f1 = __ldg(gw + xi0.y);
    float4 f2 = __ldg(gw + xi1.x);
    float4 f3 = __ldg(gw + xi1.y);
    float4 f4 = __ldg(gw + xi2.x);
    float4 f5 = __ldg(gw + xi2.y);
    if (tid < 16) cp_async16(preb + tid * 16, g_Pre + (size_t)row * 64 + tid * 4);
    asm volatile("cp.async.commit_group;" ::: "memory");
    asm volatile("cp.async.wait_group 0;" ::: "memory");
    __syncthreads();   // weights + PreBuf(row0) published

    for (; row < B_; row += NBLK) {
        // prefetch next row's index words (consumed after [3])
        int rown = row + NBLK; if (rown >= B_) rown = row;
        const int2* xrn = ((const int2*)x) + ((size_t)rown * N_ + tid) * 3;
        int2 nx0 = xrn[0], nx1 = xrn[1], nx2 = xrn[2];

        // ---- phase A: stage Geo from regs (prefetched), sigma ----
        S.Geo[ 0 * 128 + tid] = f0.y; S.Geo[ 1 * 128 + tid] = f0.z; S.Geo[ 2 * 128 + tid] = f0.w;
        S.Geo[ 3 * 128 + tid] = f1.y; S.Geo[ 4 * 128 + tid] = f1.z; S.Geo[ 5 * 128 + tid] = f1.w;
        S.Geo[ 6 * 128 + tid] = f2.y; S.Geo[ 7 * 128 + tid] = f2.z; S.Geo[ 8 * 128 + tid] = f2.w;
        S.Geo[ 9 * 128 + tid] = f3.y; S.Geo[10 * 128 + tid] = f3.z; S.Geo[11 * 128 + tid] = f3.w;
        S.Geo[12 * 128 + tid] = f4.y; S.Geo[13 * 128 + tid] = f4.z; S.Geo[14 * 128 + tid] = f4.w;
        S.Geo[15 * 128 + tid] = f5.y; S.Geo[16 * 128 + tid] = f5.z; S.Geo[17 * 128 + tid] = f5.w;

        float s = fminf(fmaxf(f0.x, 0.f), 1.f);
        s *= fminf(fmaxf(f1.x, 0.f), 1.f);
        s *= fminf(fmaxf(f2.x, 0.f), 1.f);
        s *= fminf(fmaxf(f3.x, 0.f), 1.f);
        s *= fminf(fmaxf(f4.x, 0.f), 1.f);
        s *= fminf(fmaxf(f5.x, 0.f), 1.f);
        float sigma0 = s + 1e-4f;

        float m = sigma0;
        #pragma unroll
        for (int o = 16; o > 0; o >>= 1)
            m = fmaxf(m, __shfl_xor_sync(0xffffffffu, m, o));
        if (lane == 0) S.Max[warp] = m;
        __syncthreads();  // [1] Geo, Max ready

        float rowmax = fmaxf(fmaxf(S.Max[0], S.Max[1]), fmaxf(S.Max[2], S.Max[3]));
        float sigma = sigma0 / rowmax;
        S.Sig[tid] = sigma;
        outSigma[(size_t)row * N_ + tid] = sigma;

        // ---- GEMM0: geo(18) -> 64; init from precomputed PreBuf ----
        u64 acc0[16], acc1[16];
        {
            const u64* pre = (const u64*)(S.PreBuf + cbase);
            #pragma unroll
            for (int j = 0; j < 16; j++) { acc0[j] = pre[j]; acc1[j] = pre[j]; }
        }
        #pragma unroll 6
        for (int k = 0; k < KGEO; k++) {
            u64 av = *(const u64*)(S.Geo + k * 128 + p0);
            float a0f, a1f; unpack2(av, a0f, a1f);
            u64 a0 = pack2(a0f), a1 = pack2(a1f);
            const ulonglong2* wr = (const ulonglong2*)(S.W0geo + k * 64 + cbase);
            #pragma unroll
            for (int jj = 0; jj < 8; jj++) {
                ulonglong2 w = wr[jj];
                acc0[2 * jj]     = ffma2(a0, w.x, acc0[2 * jj]);
                acc0[2 * jj + 1] = ffma2(a0, w.y, acc0[2 * jj + 1]);
                acc1[2 * jj]     = ffma2(a1, w.x, acc1[2 * jj]);
                acc1[2 * jj + 1] = ffma2(a1, w.y, acc1[2 * jj + 1]);
            }
        }
        #pragma unroll
        for (int j = 0; j < 16; j++) {
            float x0, x1, y0, y1;
            unpack2(acc0[j], x0, x1);
            unpack2(acc1[j], y0, y1);
            x0 = fmaxf(x0, 0.f); x1 = fmaxf(x1, 0.f);
            y0 = fmaxf(y0, 0.f); y1 = fmaxf(y1, 0.f);
            int c = cbase + 2 * j;
            *(u64*)(S.Act + c * 128 + p0)       = pack2f(x0, y0);
            *(u64*)(S.Act + (c + 1) * 128 + p0) = pack2f(x1, y1);
        }
        __syncthreads();  // [3] Act ready; Geo + PreBuf fully consumed

        // ---- prefetch next row: gather + Pre row (hidden under GEMM1) ----
        f0 = __ldg(gw + nx0.x);
        f1 = __ldg(gw + nx0.y);
        f2 = __ldg(gw + nx1.x);
        f3 = __ldg(gw + nx1.y);
        f4 = __ldg(gw + nx2.x);
        f5 = __ldg(gw + nx2.y);
        if (tid < 16) cp_async16(preb + tid * 16, g_Pre + (size_t)rown * 64 + tid * 4);
        asm volatile("cp.async.commit_group;" ::: "memory");

        // ---- GEMM1: 64 -> 64 ----
        {
            const u64* bb = (const u64*)(S.B1c + cbase);
            #pragma unroll
            for (int j = 0; j < 16; j++) { acc0[j] = bb[j]; acc1[j] = bb[j]; }
        }
        #pragma unroll 8
        for (int k = 0; k < 64; k++) {
            u64 av = *(const u64*)(S.Act + k * 128 + p0);
            float a0f, a1f; unpack2(av, a0f, a1f);
            u64 a0 = pack2(a0f), a1 = pack2(a1f);
            const ulonglong2* wr = (const ulonglong2*)(S.W1s + k * 64 + cbase);
            #pragma unroll
            for (int jj = 0; jj < 8; jj++) {
                ulonglong2 w = wr[jj];
                acc0[2 * jj]     = ffma2(a0, w.x, acc0[2 * jj]);
                acc0[2 * jj + 1] = ffma2(a0, w.y, acc0[2 * jj + 1]);
                acc1[2 * jj]     = ffma2(a1, w.x, acc1[2 * jj]);
                acc1[2 * jj + 1] = ffma2(a1, w.y, acc1[2 * jj + 1]);
            }
        }

        // ---- layer 2 partials (ReLU fused) ----
        float s0a = 0.f, s1a = 0.f, s2a = 0.f;
        float s0b = 0.f, s1b = 0.f, s2b = 0.f;
        #pragma unroll
        for (int j = 0; j < 16; j++) {
            float x0, x1, y0, y1;
            unpack2(acc0[j], x0, x1);
            unpack2(acc1[j], y0, y1);
            x0 = fmaxf(x0, 0.f); x1 = fmaxf(x1, 0.f);
            y0 = fmaxf(y0, 0.f); y1 = fmaxf(y1, 0.f);
            float4 q0 = S.W2q[cbase + 2 * j];
            float4 q1 = S.W2q[cbase + 2 * j + 1];
            s0a = fmaf(x0, q0.x, s0a); s0a = fmaf(x1, q1.x, s0a);
            s1a = fmaf(x0, q0.y, s1a); s1a = fmaf(x1, q1.y, s1a);
            s2a = fmaf(x0, q0.z, s2a); s2a = fmaf(x1, q1.z, s2a);
            s0b = fmaf(y0, q0.x, s0b); s0b = fmaf(y1, q1.x, s0b);
            s1b = fmaf(y0, q0.y, s1b); s1b = fmaf(y1, q1.y, s1b);
            s2b = fmaf(y0, q0.z, s2b); s2b = fmaf(y1, q1.z, s2b);
        }
        S.PSum[p0 * 2 + cg]       = make_float4(s0a, s1a, s2a, 0.f);
        S.PSum[(p0 + 1) * 2 + cg] = make_float4(s0b, s1b, s2b, 0.f);
        asm volatile("cp.async.wait_group 0;" ::: "memory");
        __syncthreads();  // [4] PSum ready; PreBuf(next) published

        // ---- finish (thread = point) ----
        float4 pa = S.PSum[tid * 2];
        float4 pb = S.PSum[tid * 2 + 1];
        float c0 = pa.x + pb.x + S.B2[0];
        float c1 = pa.y + pb.y + S.B2[1];
        float c2 = pa.z + pb.z + S.B2[2];
        c0 = 1.f / (1.f + __expf(-c0));
        c1 = 1.f / (1.f + __expf(-c1));
        c2 = 1.f / (1.f + __expf(-c2));

        float wgt = (tid == 0 ? 1.f : 1.f - S.Sig[tid - 1]) * sigma;
        float r0 = wgt * c0, r1 = wgt * c1, r2 = wgt * c2;
        #pragma unroll
        for (int o = 16; o > 0; o >>= 1) {
            r0 += __shfl_xor_sync(0xffffffffu, r0, o);
            r1 += __shfl_xor_sync(0xffffffffu, r1, o);
            r2 += __shfl_xor_sync(0xffffffffu, r2, o);
        }
        if (lane == 0) {
            S.CRed[warp * 3 + 0] = r0;
            S.CRed[warp * 3 + 1] = r1;
            S.CRed[warp * 3 + 2] = r2;
        }
        __syncthreads();  // [5] CRed ready; guards Sig/Geo reuse next row
        if (tid == 0) {
            float* oc = outColor + (size_t)row * 3;
            oc[0] = S.CRed[0] + S.CRed[3] + S.CRed[6] + S.CRed[9];
            oc[1] = S.CRed[1] + S.CRed[4] + S.CRed[7] + S.CRed[10];
            oc[2] = S.CRed[2] + S.CRed[5] + S.CRed[8] + S.CRed[11];
        }
    }
}

extern "C" void kernel_launch(void* const* d_in, const int* in_sizes, int n_in,
                              void* d_out, int out_size)
{
    const int*    x    = (const int*)d_in[0];
    const float*  dirg = (const float*)d_in[1];
    const float4* gw   = (const float4*)d_in[2];
    const float*  W0   = (const float*)d_in[3];
    const float*  b0   = (const float*)d_in[4];
    const float*  W1   = (const float*)d_in[5];
    const float*  b1   = (const float*)d_in[6];
    const float*  W2   = (const float*)d_in[7];
    const float*  b2   = (const float*)d_in[8];

    float* outSigma = (float*)d_out;                  // (B, N, 1) flattened
    float* outColor = outSigma + (size_t)B_ * N_;     // (B, 3) flattened

    pre_kernel<<<B_ / 2, 128>>>(dirg, W0, b0);

    int smem = (int)sizeof(Smem);
    cudaFuncSetAttribute(surfnet_kernel,
                         cudaFuncAttributeMaxDynamicSharedMemorySize, smem);
    surfnet_kernel<<<NBLK, NTHR, smem>>>(x, gw, W0, b0, W1, b1, W2, b2,
                                         outSigma, outColor);
}